// round 17
// baseline (speedup 1.0000x reference)
#include <cuda_runtime.h>
#include <math.h>

#define B 8
#define T 2048
#define H 1024
#define V 256
#define GRID 128
#define NTHR 384         // 8 MMA warps + 4 epilogue warps
#define UPC 8            // hidden units per CTA

typedef unsigned long long ull;

#define PPC 16           // positions per loss chunk
#define CHUNKS 8         // 128 positions per CTA
#define FLAG_STRIDE 8    // 32-byte padded flags

// lstm-phase SMEM:
//   h_s  [8 warps][8 b][132] f32  = 33792 B  (per-warp private K-slice)
//   part [2 parity][8 w][292] f32 = 18688 B
//   bias [32] f32
#define PH_HS    0
#define PH_PART  33792
#define PH_BIAS  52480
// loss-phase SMEM: h[PPC][1024] | logits[PPC][256] | red[PPC]
#define SMEM_DYN (PPC*1024*4 + PPC*256*4 + 64)

// ---------------- device scratch (static; no allocation) ----------------
__device__ float    g_hs[B * T * H];             // hidden states, [t][b][j]
__device__ float    g_hbuf[2][B][H];             // double-buffered h
__device__ unsigned g_flags[GRID * FLAG_STRIDE]; // monotonic per-CTA counters
__device__ float    g_partials[GRID];
__device__ unsigned g_ticket;

// ---------------- helpers ----------------
__device__ __forceinline__ ull fma2(ull a, ull b, ull c) {
    ull d;
    asm("fma.rn.f32x2 %0, %1, %2, %3;" : "=l"(d) : "l"(a), "l"(b), "l"(c));
    return d;
}
__device__ __forceinline__ float2 unpk(ull v) {
    float2 r;
    asm("mov.b64 {%0, %1}, %2;" : "=f"(r.x), "=f"(r.y) : "l"(v));
    return r;
}
__device__ __forceinline__ unsigned ld_cgv(const unsigned* p) {
    unsigned v;
    asm volatile("ld.global.cg.u32 %0, [%1];" : "=r"(v) : "l"(p));
    return v;
}
__device__ __forceinline__ unsigned ld_acq(const unsigned* p) {
    unsigned v;
    asm volatile("ld.acquire.gpu.global.u32 %0, [%1];" : "=r"(v) : "l"(p));
    return v;
}
__device__ __forceinline__ void red_rel_add(unsigned* p, unsigned v) {
    asm volatile("red.release.gpu.global.add.u32 [%0], %1;" :: "l"(p), "r"(v) : "memory");
}
__device__ __forceinline__ void fence_acq() {
    asm volatile("fence.acq_rel.gpu;" ::: "memory");
}
__device__ __forceinline__ float tanh_fast(float x) {
    return 2.0f / (1.0f + __expf(-2.0f * x)) - 1.0f;
}
__device__ __forceinline__ float sigmoid_fast(float x) {
    return 1.0f / (1.0f + __expf(-x));
}
__device__ __forceinline__ unsigned f2tf32(float f) {
    unsigned r;
    asm("cvt.rna.tf32.f32 %0, %1;" : "=r"(r) : "f"(f));
    return r;
}
// m16n8k8 tf32 MMA, fp32 accumulate
__device__ __forceinline__ void mma_tf32(float* d, const unsigned* a,
                                         unsigned b0, unsigned b1) {
    asm volatile(
        "mma.sync.aligned.m16n8k8.row.col.f32.tf32.tf32.f32 "
        "{%0,%1,%2,%3}, {%4,%5,%6,%7}, {%8,%9}, {%0,%1,%2,%3};"
        : "+f"(d[0]), "+f"(d[1]), "+f"(d[2]), "+f"(d[3])
        : "r"(a[0]), "r"(a[1]), "r"(a[2]), "r"(a[3]), "r"(b0), "r"(b1));
}

// ---------------- single fused persistent kernel ----------------
__global__ void __launch_bounds__(NTHR, 1)
charrnn_kernel(const int* __restrict__ Xs,
               const int* __restrict__ ys,
               const float* __restrict__ W_ih,
               const float* __restrict__ W_hh,
               const float* __restrict__ b_ih,
               const float* __restrict__ b_hh,
               const float* __restrict__ W1,
               const float* __restrict__ b1,
               float* __restrict__ out)
{
    extern __shared__ char smem[];
    float* h_s    = (float*)(smem + PH_HS);      // [8][8][132]
    float* part   = (float*)(smem + PH_PART);    // [2][8][292]
    float* bias_s = (float*)(smem + PH_BIAS);    // [32] (g*8+u)
    __shared__ int s_win;

    const int tid  = threadIdx.x;
    const int wid  = tid >> 5;
    const int lane = tid & 31;
    const int cta  = blockIdx.x;
    const int j0   = cta * UPC;
    const int mwid = wid & 7;                    // clamp for safe addressing

    // monotonic flag base (flag advances by 4 per step: one per epilogue warp)
    unsigned* myflag = &g_flags[cta * FLAG_STRIDE];
    const unsigned fbase = ld_cgv(myflag);
    // per-lane poll target for MMA warps
    const unsigned* pollflag = &g_flags[(16 * mwid + (lane >> 1)) * FLAG_STRIDE];
    // warp-0 end-phase poll targets
    const unsigned* fl0 = &g_flags[(lane)      * FLAG_STRIDE];
    const unsigned* fl1 = &g_flags[(lane + 32) * FLAG_STRIDE];
    const unsigned* fl2 = &g_flags[(lane + 64) * FLAG_STRIDE];
    const unsigned* fl3 = &g_flags[(lane + 96) * FLAG_STRIDE];

    // ---- A fragments (MMA warps only): warp mwid owns K-slice [mwid*128, +128)
    unsigned wA[2][16][4];
    if (wid < 8) {
        const int ks = mwid * 128;
        const int rlo = lane >> 2;
        const int kc  = lane & 3;
        #pragma unroll
        for (int m = 0; m < 2; ++m) {
            #pragma unroll
            for (int k8 = 0; k8 < 16; ++k8) {
                int r0 = m * 16 + rlo;
                int r1 = r0 + 8;
                int kk = ks + k8 * 8 + kc;
                int g0 = r0 >> 3, u0g = r0 & 7;
                int g1 = r1 >> 3, u1g = r1 & 7;
                const float* row0 = &W_hh[(g0 * H + j0 + u0g) * H];
                const float* row1 = &W_hh[(g1 * H + j0 + u1g) * H];
                wA[m][k8][0] = f2tf32(row0[kk]);
                wA[m][k8][1] = f2tf32(row1[kk]);
                wA[m][k8][2] = f2tf32(row0[kk + 4]);
                wA[m][k8][3] = f2tf32(row1[kk + 4]);
            }
        }
    }
    if (tid < 32) {
        int g = tid >> 3, u = tid & 7;
        bias_s[tid] = b_ih[g * H + j0 + u] + b_hh[g * H + j0 + u];
    }
    // zero private h slices (t=0 uses h=0)
    for (int i = tid; i < 8 * 8 * 132; i += NTHR) h_s[i] = 0.0f;
    __syncthreads();

    float* h_sw = &h_s[mwid * 1056];
    const float* hB = &h_sw[(lane >> 2) * 132 + (lane & 3)];
    float* pw0 = &part[mwid * 292];
    float* pw1 = &part[2336 + mwid * 292];
    const int prow = lane >> 2, pcol = 2 * (lane & 3);

    // epilogue constants (warps 8..11): etid 0..127, 2 threads per cell
    const int etid = tid - 256;
    const int ecell = etid >> 1;                 // 0..63
    const int ehalf = etid & 1;                  // 0: w=0..3, 1: w=4..7
    const int eu = ecell & 7, eb = ecell >> 3;
    const int ej = j0 + eu;
    float c_reg = 0.0f;

    // ================= recurrence (warp-specialized, blocking barrier) ======
    if (wid < 8) {
        // ---------- MMA warps ----------
        for (int t = 0; t < T; ++t) {
            if (t > 0) {
                // acquire-poll: passing iteration doubles as the ordering acquire
                const unsigned tgt = fbase + 4u * (unsigned)t;
                while (ld_acq(pollflag) < tgt) { }
                const float4* hb = (const float4*)g_hbuf[t & 1];
                #pragma unroll
                for (int b2 = 0; b2 < B; ++b2) {
                    float4 v = __ldcg(hb + b2 * 256 + 32 * mwid + lane);
                    *(float4*)&h_sw[b2 * 132 + 4 * lane] = v;
                }
                __syncwarp();
            }

            float d0[4] = {0.f, 0.f, 0.f, 0.f};
            float d1[4] = {0.f, 0.f, 0.f, 0.f};
            #pragma unroll
            for (int k8 = 0; k8 < 16; ++k8) {
                float bf0 = hB[k8 * 8];
                float bf1 = hB[k8 * 8 + 4];
                unsigned b0 = f2tf32(bf0), b1 = f2tf32(bf1);
                mma_tf32(d0, wA[0][k8], b0, b1);
                mma_tf32(d1, wA[1][k8], b0, b1);
            }
            __syncwarp();                        // WAR: h_sw reuse next step

            float* pw = (t & 1) ? pw1 : pw0;
            pw[(prow     ) * 9 + pcol    ] = d0[0];
            pw[(prow     ) * 9 + pcol + 1] = d0[1];
            pw[(prow +  8) * 9 + pcol    ] = d0[2];
            pw[(prow +  8) * 9 + pcol + 1] = d0[3];
            pw[(prow + 16) * 9 + pcol    ] = d1[0];
            pw[(prow + 16) * 9 + pcol + 1] = d1[1];
            pw[(prow + 24) * 9 + pcol    ] = d1[2];
            pw[(prow + 24) * 9 + pcol + 1] = d1[3];
            asm volatile("bar.sync 1, %0;" :: "n"(NTHR) : "memory");
            // proceed to t+1 (epilogue overlaps)
        }
    } else {
        // ---------- epilogue warps (128 threads, 2 per cell) ----------
        for (int t = 0; t < T; ++t) {
            // prefetch input contribution (half 0 only; latency drains under bar)
            float wi0 = 0.f, wi1 = 0.f, wi2 = 0.f, wi3 = 0.f;
            if (ehalf == 0) {
                int x = __ldg(&Xs[eb * T + t]);
                wi0 = __ldg(&W_ih[(0*H + ej) * V + x]);
                wi1 = __ldg(&W_ih[(1*H + ej) * V + x]);
                wi2 = __ldg(&W_ih[(2*H + ej) * V + x]);
                wi3 = __ldg(&W_ih[(3*H + ej) * V + x]);
            }

            asm volatile("bar.sync 1, %0;" :: "n"(NTHR) : "memory");

            const float* pbase = &part[(t & 1) ? 2336 : 0];
            float S0 = 0.f, S1 = 0.f, S2 = 0.f, S3 = 0.f;
            #pragma unroll
            for (int wql = 0; wql < 4; ++wql) {
                const float* pp = pbase + (ehalf * 4 + wql) * 292;
                S0 += pp[(0*8 + eu) * 9 + eb];
                S1 += pp[(1*8 + eu) * 9 + eb];
                S2 += pp[(2*8 + eu) * 9 + eb];
                S3 += pp[(3*8 + eu) * 9 + eb];
            }
            // combine the two halves (adjacent lanes)
            S0 += __shfl_xor_sync(0xffffffffu, S0, 1);
            S1 += __shfl_xor_sync(0xffffffffu, S1, 1);
            S2 += __shfl_xor_sync(0xffffffffu, S2, 1);
            S3 += __shfl_xor_sync(0xffffffffu, S3, 1);

            if (ehalf == 0) {
                S0 += wi0 + bias_s[0*8 + eu];
                S1 += wi1 + bias_s[1*8 + eu];
                S2 += wi2 + bias_s[2*8 + eu];
                S3 += wi3 + bias_s[3*8 + eu];
                float ig = sigmoid_fast(S0);
                float fg = sigmoid_fast(S1);
                float gg = tanh_fast(S2);
                float og = sigmoid_fast(S3);
                c_reg = fg * c_reg + ig * gg;
                float hnew = og * tanh_fast(c_reg);
                g_hbuf[(t + 1) & 1][eb][ej] = hnew;
                // archive (consumed only after end-phase global barrier)
                g_hs[(t * B + eb) * H + ej] = hnew;
            }
            // per-warp release publish: flag += 1 from each epilogue warp
            __syncwarp();
            if (lane == 0) red_rel_add(myflag, 1u);
        }
    }

    // ---- publish archives; wait for all CTAs ----
    // flags now at fbase + 4*T; end-phase adds +1 -> fbase + 4*T + 1
    __threadfence();
    __syncthreads();
    if (tid == 0) red_rel_add(myflag, 1u);
    if (wid == 0) {
        const unsigned tgt = fbase + 4u * (unsigned)T + 1u;
        bool d0 = false, d1 = false, d2 = false, d3 = false;
        while (true) {
            if (!d0) d0 = ld_cgv(fl0) >= tgt;
            if (!d1) d1 = ld_cgv(fl1) >= tgt;
            if (!d2) d2 = ld_cgv(fl2) >= tgt;
            if (!d3) d3 = ld_cgv(fl3) >= tgt;
            if (__all_sync(0xffffffffu, d0 && d1 && d2 && d3)) break;
            __nanosleep(64);
        }
        fence_acq();
    }
    __syncthreads();

    // ================= loss phase: 128 positions per CTA =================
    float* h_sm     = (float*)smem;                              // [PPC][1024]
    float* logit_sm = (float*)(smem + PPC*1024*4);               // [PPC][256]
    float* redp     = (float*)(smem + PPC*1024*4 + PPC*256*4);   // [PPC]

    float cta_sum = 0.0f;

    for (int chunk = 0; chunk < CHUNKS; ++chunk) {
        const int pos0 = cta * 128 + chunk * PPC;                // pos = t*B + b

        for (int idx4 = tid; idx4 < PPC * 1024 / 4; idx4 += NTHR) {
            *(float4*)&h_sm[idx4 * 4] =
                __ldcg((const float4*)&g_hs[pos0 * 1024] + idx4);
        }
        __syncthreads();

        if (tid < 256) {
            ull acc2[PPC];
            #pragma unroll
            for (int p = 0; p < PPC; ++p) acc2[p] = 0ull;

            const ulonglong2* wrow = (const ulonglong2*)&W1[tid * 1024];
            for (int k4 = 0; k4 < 256; ++k4) {
                ulonglong2 w = __ldg(wrow + k4);
                #pragma unroll
                for (int p = 0; p < PPC; ++p) {
                    ulonglong2 hv = *(const ulonglong2*)&h_sm[p * 1024 + k4 * 4];
                    acc2[p] = fma2(w.x, hv.x, acc2[p]);
                    acc2[p] = fma2(w.y, hv.y, acc2[p]);
                }
            }
            float bv = b1[tid];
            #pragma unroll
            for (int p = 0; p < PPC; ++p) {
                float2 f = unpk(acc2[p]);
                logit_sm[p * 256 + tid] = f.x + f.y + bv;
            }
        }
        __syncthreads();

        if (wid < 8) {
            #pragma unroll
            for (int pp = 0; pp < 2; ++pp) {
                int p = wid * 2 + pp;
                const float* L = &logit_sm[p * 256];
                float vv[8];
                #pragma unroll
                for (int i = 0; i < 8; ++i) vv[i] = L[lane + 32 * i];
                float m = vv[0];
                #pragma unroll
                for (int i = 1; i < 8; ++i) m = fmaxf(m, vv[i]);
                for (int off = 16; off; off >>= 1)
                    m = fmaxf(m, __shfl_xor_sync(0xffffffffu, m, off));
                float s = 0.0f;
                #pragma unroll
                for (int i = 0; i < 8; ++i) s += expf(vv[i] - m);
                for (int off = 16; off; off >>= 1)
                    s += __shfl_xor_sync(0xffffffffu, s, off);
                if (lane == 0) {
                    int pos = pos0 + p;
                    int b   = pos & 7;
                    int t   = pos >> 3;
                    int y   = __ldg(&ys[b * T + t]);
                    redp[p] = (m + logf(s)) - L[y];
                }
            }
        }
        __syncthreads();
        if (tid == 0) {
            float ssum = 0.0f;
            #pragma unroll
            for (int p = 0; p < PPC; ++p) ssum += redp[p];
            cta_sum += ssum;
        }
        __syncthreads();
    }

    // ---- deterministic final reduction by the last-arriving CTA ----
    if (tid == 0) {
        g_partials[cta] = cta_sum;
        __threadfence();
        unsigned old = atomicAdd(&g_ticket, 1u);
        s_win = ((old % GRID) == (GRID - 1)) ? 1 : 0;
    }
    __syncthreads();
    if (s_win) {
        __threadfence();
        float* r2 = (float*)smem;
        if (tid < GRID) r2[tid] = __ldcg(&g_partials[tid]);
        __syncthreads();
        for (int off = 64; off; off >>= 1) {
            if (tid < off) r2[tid] += r2[tid + off];
            __syncthreads();
        }
        if (tid == 0) out[0] = r2[0] / (float)(B * T);
    }
}

// ---------------- launch ----------------
extern "C" void kernel_launch(void* const* d_in, const int* in_sizes, int n_in,
                              void* d_out, int out_size)
{
    const int*   Xs   = (const int*)d_in[0];
    const int*   ys   = (const int*)d_in[1];
    /* d_in[2] = predict (always 0 here) */
    const float* W_ih = (const float*)d_in[3];
    const float* W_hh = (const float*)d_in[4];
    const float* b_ih = (const float*)d_in[5];
    const float* b_hh = (const float*)d_in[6];
    const float* W1   = (const float*)d_in[7];
    const float* b1   = (const float*)d_in[8];
    float* out = (float*)d_out;

    cudaFuncSetAttribute(charrnn_kernel,
                         cudaFuncAttributeMaxDynamicSharedMemorySize, SMEM_DYN);

    charrnn_kernel<<<GRID, NTHR, SMEM_DYN>>>(Xs, ys, W_ih, W_hh, b_ih, b_hh,
                                             W1, b1, out);
    (void)in_sizes; (void)n_in; (void)out_size;
}